// round 10
// baseline (speedup 1.0000x reference)
#include <cuda_runtime.h>

#define NIMG_MAX 64
#define HH 1024
#define WW 1024
#define NB 131072         // 256 * 512 bins per image
#define TH 64             // rows per stripe
#define NSTRIPE (HH / TH) // 16 blocks per image

// 32 MB histogram (zeroed by a graph memset node each invocation)
__device__ __align__(16) int   g_hist[NIMG_MAX * NB];
__device__ __align__(16) float g_ent[NIMG_MAX];      // per-image entropy
__device__ unsigned int g_done_img[NIMG_MAX];        // zero-init; self-resetting
__device__ unsigned int g_fin;                       // zero-init; self-resetting

// ---------------------------------------------------------------- histogram
// Register-resident sliding window, 4-row software pipeline.
// Halo columns via warp SHFL; lanes 0/31 use a 1-sector predicated LDG.
// The 16th block to finish an image scans its histogram (entropy) in-kernel;
// the last image-completer reduces the 64 entropies to the output scalar.

struct Row6 { int v0, v1, v2, v3, vl, vr; };

__device__ __forceinline__ Row6 load_row(const float* __restrict__ p, bool valid,
                                         int lane, bool lv, bool rv) {
    Row6 r;
    float e = 0.0f;
    if (valid) {
        if (lane == 0  && lv) e = __ldg(p - 1);
        if (lane == 31 && rv) e = __ldg(p + 4);
        float4 f = *(const float4*)p;
        r.v0 = (int)(f.x * 255.0f);
        r.v1 = (int)(f.y * 255.0f);
        r.v2 = (int)(f.z * 255.0f);
        r.v3 = (int)(f.w * 255.0f);
    } else {
        r.v0 = r.v1 = r.v2 = r.v3 = 0;
    }
    int ei = (int)(e * 255.0f);
    int up = __shfl_up_sync(0xffffffffu, r.v3, 1);
    int dn = __shfl_down_sync(0xffffffffu, r.v0, 1);
    r.vl = (lane == 0)  ? (valid && lv ? ei : 0) : up;
    r.vr = (lane == 31) ? (valid && rv ? ei : 0) : dn;
    if (!valid) { r.vl = 0; r.vr = 0; }
    return r;
}

template<bool SPEC>
__device__ __forceinline__ void hist_body(const float* __restrict__ p, int ry0,
                                          int* __restrict__ hist,
                                          int lane, bool lv, bool rv) {
    Row6 t = load_row(p, ry0 > 0, lane, lv, rv);         p += WW;
    Row6 m = load_row(p, true, lane, lv, rv);            p += WW;

    int st0 = t.vl + t.v0 + t.v1, st1 = t.v0 + t.v1 + t.v2;
    int st2 = t.v1 + t.v2 + t.v3, st3 = t.v2 + t.v3 + t.vr;
    int sm0 = m.vl + m.v1, sm1 = m.v0 + m.v2;
    int sm2 = m.v1 + m.v3, sm3 = m.v2 + m.vr;
    int c0 = m.v0, c1 = m.v1, c2 = m.v2, c3 = m.v3;

    #pragma unroll 1
    for (int rb = 0; rb < TH; rb += 4) {
        // front-load 4 rows: 4 independent LDG.128 in flight before any use
        Row6 b[4];
        #pragma unroll
        for (int j = 0; j < 4; ++j)
            b[j] = load_row(p + j * WW, ry0 + rb + j + 1 < HH, lane, lv, rv);
        p += 4 * WW;

        #pragma unroll
        for (int j = 0; j < 4; ++j) {
            int sb0 = b[j].vl + b[j].v0 + b[j].v1;
            int sb1 = b[j].v0 + b[j].v1 + b[j].v2;
            int sb2 = b[j].v1 + b[j].v2 + b[j].v3;
            int sb3 = b[j].v2 + b[j].v3 + b[j].vr;

            int n0 = st0 + sm0 + sb0;
            int n1 = st1 + sm1 + sb1;
            int n2 = st2 + sm2 + sb2;
            int n3 = st3 + sm3 + sb3;

            // (nb*13108)>>16 == trunc(nb/5); 21846 -> trunc(nb/3)
            int mul = 13108;
            if (SPEC) {
                int gr = ry0 + rb + j;
                mul = (gr == 0 || gr == HH - 1) ? 21846 : 13108;
            }
            atomicAdd(&hist[(c0 << 9) + ((n0 * mul) >> 16)], 1);
            atomicAdd(&hist[(c1 << 9) + ((n1 * mul) >> 16)], 1);
            atomicAdd(&hist[(c2 << 9) + ((n2 * mul) >> 16)], 1);
            atomicAdd(&hist[(c3 << 9) + ((n3 * mul) >> 16)], 1);

            st0 = sm0 + c0; st1 = sm1 + c1; st2 = sm2 + c2; st3 = sm3 + c3;
            sm0 = sb0 - b[j].v0; sm1 = sb1 - b[j].v1;
            sm2 = sb2 - b[j].v2; sm3 = sb3 - b[j].v3;
            c0 = b[j].v0; c1 = b[j].v1; c2 = b[j].v2; c3 = b[j].v3;
        }
    }
}

__global__ __launch_bounds__(256) void k_hist(const float* __restrict__ x,
                                              float* __restrict__ out, int B) {
    const int img = blockIdx.z;
    const int ry0 = blockIdx.y * TH;
    const int c    = threadIdx.x * 4;           // 256 threads * 4 = 1024 cols
    const int lane = threadIdx.x & 31;
    const int tid  = threadIdx.x;
    const bool lv = (c > 0);
    const bool rv = (c + 4 < WW);

    const float* p = x + (size_t)img * (HH * (size_t)WW) + (size_t)(ry0 - 1) * WW + c;
    int* hist = g_hist + img * NB;

    const bool spec = (img == 0 || img == B - 1) &&
                      (blockIdx.y == 0 || blockIdx.y == NSTRIPE - 1);
    if (spec) hist_body<true >(p, ry0, hist, lane, lv, rv);
    else      hist_body<false>(p, ry0, hist, lane, lv, rv);

    // ---- image-completion handoff ----
    __shared__ bool s_last;
    __shared__ float sm[256];
    __threadfence();                       // drain this block's REDs
    __syncthreads();
    if (tid == 0) {
        unsigned v = atomicAdd(&g_done_img[img], 1u);
        s_last = (v == NSTRIPE - 1);       // all 16 blocks' REDs visible
    }
    __syncthreads();
    if (!s_last) return;

    // ---- per-image entropy scan (one block, likely L2-resident data) ----
    const int4* h4 = (const int4*)hist;
    float acc = 0.0f;
    #pragma unroll 4
    for (int i = tid; i < NB / 4; i += 256) {
        int4 v = h4[i];
        if (v.x) acc += (float)v.x * __log2f((float)v.x);
        if (v.y) acc += (float)v.y * __log2f((float)v.y);
        if (v.z) acc += (float)v.z * __log2f((float)v.z);
        if (v.w) acc += (float)v.w * __log2f((float)v.w);
    }
    sm[tid] = acc;
    __syncthreads();
    for (int s = 128; s > 0; s >>= 1) {
        if (tid < s) sm[tid] += sm[tid + s];
        __syncthreads();
    }

    __shared__ bool s_fin;
    if (tid == 0) {
        g_ent[img] = 20.0f - sm[0] * (1.0f / 1048576.0f);  // log2(2^20)-sum/2^20
        g_done_img[img] = 0;               // reset for next graph replay
        __threadfence();
        unsigned v = atomicAdd(&g_fin, 1u);
        s_fin = (v == (unsigned)B - 1);
    }
    __syncthreads();
    if (!s_fin) return;

    // ---- final mean over fixed slots (deterministic tree) ----
    float e = (tid < B) ? g_ent[tid] : 0.0f;
    sm[tid] = e;
    __syncthreads();
    for (int s = 128; s > 0; s >>= 1) {
        if (tid < s) sm[tid] += sm[tid + s];
        __syncthreads();
    }
    if (tid == 0) {
        out[0] = sm[0] / (float)B;
        g_fin = 0;                         // reset for next graph replay
    }
}

// ---------------------------------------------------------------- launch
extern "C" void kernel_launch(void* const* d_in, const int* in_sizes, int n_in,
                              void* d_out, int out_size) {
    const float* x = (const float*)d_in[0];
    int B = in_sizes[0] / (HH * WW);
    if (B > NIMG_MAX) B = NIMG_MAX;

    // bulk zero of the used histogram range: captured as a graph memset node
    void* hp = nullptr;
    cudaGetSymbolAddress(&hp, g_hist);
    cudaMemsetAsync(hp, 0, (size_t)B * NB * sizeof(int));

    dim3 gh(1, NSTRIPE, B);          // 1 x 16 x 64 = 1024 blocks
    k_hist<<<gh, 256>>>(x, (float*)d_out, B);
}

// round 11
// speedup vs baseline: 1.6005x; 1.6005x over previous
#include <cuda_runtime.h>

#define NIMG_MAX 64
#define HH 1024
#define WW 1024
#define NB 131072         // 256 * 512 bins per image
#define EBLK 32           // entropy partial blocks per image
#define TH 64             // rows per stripe
#define NSTRIPE (HH / TH)

// 32 MB histogram scratch (zeroed by a graph memset node each invocation).
// Phase discipline (hard-won): memset writes it, k_hist REDs it, k_entropy
// reads it — never concurrently (concurrent read poisons the LTS atomic pipe).
__device__ __align__(16) int   g_hist[NIMG_MAX * NB];
__device__ __align__(16) float g_partial[NIMG_MAX * EBLK];
__device__ unsigned int g_done;   // zero-init; reset by last entropy block

// ---------------------------------------------------------------- histogram
// Register-resident sliding window, 4-row software pipeline.
// Halo columns via warp SHFL; lanes 0/31 use a 1-sector predicated LDG.

struct Row6 { int v0, v1, v2, v3, vl, vr; };

__device__ __forceinline__ Row6 load_row(const float* __restrict__ p, bool valid,
                                         int lane, bool lv, bool rv) {
    Row6 r;
    float e = 0.0f;
    if (valid) {
        if (lane == 0  && lv) e = __ldg(p - 1);
        if (lane == 31 && rv) e = __ldg(p + 4);
        float4 f = *(const float4*)p;
        r.v0 = (int)(f.x * 255.0f);
        r.v1 = (int)(f.y * 255.0f);
        r.v2 = (int)(f.z * 255.0f);
        r.v3 = (int)(f.w * 255.0f);
    } else {
        r.v0 = r.v1 = r.v2 = r.v3 = 0;
    }
    int ei = (int)(e * 255.0f);
    int up = __shfl_up_sync(0xffffffffu, r.v3, 1);
    int dn = __shfl_down_sync(0xffffffffu, r.v0, 1);
    r.vl = (lane == 0)  ? (valid && lv ? ei : 0) : up;
    r.vr = (lane == 31) ? (valid && rv ? ei : 0) : dn;
    if (!valid) { r.vl = 0; r.vr = 0; }
    return r;
}

template<bool SPEC>
__device__ __forceinline__ void hist_body(const float* __restrict__ p, int ry0,
                                          int* __restrict__ hist,
                                          int lane, bool lv, bool rv) {
    Row6 t = load_row(p, ry0 > 0, lane, lv, rv);         p += WW;
    Row6 m = load_row(p, true, lane, lv, rv);            p += WW;

    int st0 = t.vl + t.v0 + t.v1, st1 = t.v0 + t.v1 + t.v2;
    int st2 = t.v1 + t.v2 + t.v3, st3 = t.v2 + t.v3 + t.vr;
    int sm0 = m.vl + m.v1, sm1 = m.v0 + m.v2;
    int sm2 = m.v1 + m.v3, sm3 = m.v2 + m.vr;
    int c0 = m.v0, c1 = m.v1, c2 = m.v2, c3 = m.v3;

    #pragma unroll 1
    for (int rb = 0; rb < TH; rb += 4) {
        // front-load 4 rows: 4 independent LDG.128 in flight before any use
        Row6 b[4];
        #pragma unroll
        for (int j = 0; j < 4; ++j)
            b[j] = load_row(p + j * WW, ry0 + rb + j + 1 < HH, lane, lv, rv);
        p += 4 * WW;

        #pragma unroll
        for (int j = 0; j < 4; ++j) {
            int sb0 = b[j].vl + b[j].v0 + b[j].v1;
            int sb1 = b[j].v0 + b[j].v1 + b[j].v2;
            int sb2 = b[j].v1 + b[j].v2 + b[j].v3;
            int sb3 = b[j].v2 + b[j].v3 + b[j].vr;

            int n0 = st0 + sm0 + sb0;
            int n1 = st1 + sm1 + sb1;
            int n2 = st2 + sm2 + sb2;
            int n3 = st3 + sm3 + sb3;

            // (nb*13108)>>16 == trunc(nb/5); 21846 -> trunc(nb/3)
            int mul = 13108;
            if (SPEC) {
                int gr = ry0 + rb + j;
                mul = (gr == 0 || gr == HH - 1) ? 21846 : 13108;
            }
            atomicAdd(&hist[(c0 << 9) + ((n0 * mul) >> 16)], 1);
            atomicAdd(&hist[(c1 << 9) + ((n1 * mul) >> 16)], 1);
            atomicAdd(&hist[(c2 << 9) + ((n2 * mul) >> 16)], 1);
            atomicAdd(&hist[(c3 << 9) + ((n3 * mul) >> 16)], 1);

            st0 = sm0 + c0; st1 = sm1 + c1; st2 = sm2 + c2; st3 = sm3 + c3;
            sm0 = sb0 - b[j].v0; sm1 = sb1 - b[j].v1;
            sm2 = sb2 - b[j].v2; sm3 = sb3 - b[j].v3;
            c0 = b[j].v0; c1 = b[j].v1; c2 = b[j].v2; c3 = b[j].v3;
        }
    }
}

__global__ __launch_bounds__(256) void k_hist(const float* __restrict__ x, int B) {
    const int img = blockIdx.z;
    const int ry0 = blockIdx.y * TH;
    const int c    = threadIdx.x * 4;           // 256 threads * 4 = 1024 cols
    const int lane = threadIdx.x & 31;
    const bool lv = (c > 0);
    const bool rv = (c + 4 < WW);

    const float* p = x + (size_t)img * (HH * (size_t)WW) + (size_t)(ry0 - 1) * WW + c;
    int* hist = g_hist + img * NB;

    const bool spec = (img == 0 || img == B - 1) &&
                      (blockIdx.y == 0 || blockIdx.y == NSTRIPE - 1);
    if (spec) hist_body<true >(p, ry0, hist, lane, lv, rv);
    else      hist_body<false>(p, ry0, hist, lane, lv, rv);
}

// ---------------------------------------------------------------- entropy (+ final)
// Read-only over the histogram; 2048 blocks for a smooth last wave.
__global__ __launch_bounds__(256) void k_entropy(float* __restrict__ out, int B) {
    const int img = blockIdx.y;
    const int4* h = (const int4*)(g_hist + img * NB);
    const int n4 = NB / 4;

    float acc = 0.0f;
    #pragma unroll 4
    for (int i = blockIdx.x * blockDim.x + threadIdx.x; i < n4;
         i += gridDim.x * blockDim.x) {
        int4 v = h[i];
        if (v.x) acc += (float)v.x * __log2f((float)v.x);
        if (v.y) acc += (float)v.y * __log2f((float)v.y);
        if (v.z) acc += (float)v.z * __log2f((float)v.z);
        if (v.w) acc += (float)v.w * __log2f((float)v.w);
    }

    __shared__ float sm[256];
    __shared__ bool last;
    sm[threadIdx.x] = acc;
    __syncthreads();
    for (int s = 128; s > 0; s >>= 1) {
        if (threadIdx.x < s) sm[threadIdx.x] += sm[threadIdx.x + s];
        __syncthreads();
    }
    if (threadIdx.x == 0) {
        g_partial[img * EBLK + blockIdx.x] = sm[0];   // fixed slot: deterministic
        __threadfence();
        unsigned v = atomicAdd(&g_done, 1u);
        last = (v == gridDim.x * gridDim.y - 1);
    }
    __syncthreads();

    if (last) {
        const int t = threadIdx.x;
        float e = 0.0f;
        if (t < B) {
            float s = 0.0f;
            #pragma unroll
            for (int j = 0; j < EBLK; ++j) s += g_partial[t * EBLK + j];
            e = 20.0f - s * (1.0f / 1048576.0f);   // log2(2^20) - sum/2^20
        }
        __syncthreads();
        sm[t] = (t < 64) ? e : 0.0f;
        __syncthreads();
        for (int s = 32; s > 0; s >>= 1) {
            if (t < s) sm[t] += sm[t + s];
            __syncthreads();
        }
        if (t == 0) {
            out[0] = sm[0] / (float)B;
            g_done = 0;                 // reset for next graph replay
        }
    }
}

// ---------------------------------------------------------------- launch
extern "C" void kernel_launch(void* const* d_in, const int* in_sizes, int n_in,
                              void* d_out, int out_size) {
    const float* x = (const float*)d_in[0];
    int B = in_sizes[0] / (HH * WW);
    if (B > NIMG_MAX) B = NIMG_MAX;

    // bulk zero of the used histogram range: captured as a graph memset node
    void* hp = nullptr;
    cudaGetSymbolAddress(&hp, g_hist);
    cudaMemsetAsync(hp, 0, (size_t)B * NB * sizeof(int));

    dim3 gh(1, NSTRIPE, B);          // 1 x 16 x 64 = 1024 blocks
    k_hist<<<gh, 256>>>(x, B);

    k_entropy<<<dim3(EBLK, B), 256>>>((float*)d_out, B);
}

// round 13
// speedup vs baseline: 1.6037x; 1.0020x over previous
#include <cuda_runtime.h>

#define NIMG_MAX 64
#define HH 1024
#define WW 1024
#define NB 131072         // 256 * 512 bins per image
#define EBLK 16           // entropy partial blocks per image
#define TH 64             // rows per stripe
#define NSTRIPE (HH / TH)
#define LUTN 1024         // c*log2(c) table size (counts far below this)

// 32 MB histogram scratch (zeroed by a graph memset node each invocation).
// Phase discipline (hard-won): memset writes it, k_hist REDs it, k_entropy
// reads it — never concurrently (concurrent read poisons the LTS atomic pipe).
__device__ __align__(16) int   g_hist[NIMG_MAX * NB];
__device__ __align__(16) float g_partial[NIMG_MAX * EBLK];
__device__ unsigned int g_done;   // zero-init; reset by last entropy block

// ---------------------------------------------------------------- histogram
// Register-resident sliding window, 4-row software pipeline.
// Halo columns via warp SHFL; lanes 0/31 use a 1-sector predicated LDG.

struct Row6 { int v0, v1, v2, v3, vl, vr; };

__device__ __forceinline__ Row6 load_row(const float* __restrict__ p, bool valid,
                                         int lane, bool lv, bool rv) {
    Row6 r;
    float e = 0.0f;
    if (valid) {
        if (lane == 0  && lv) e = __ldg(p - 1);
        if (lane == 31 && rv) e = __ldg(p + 4);
        float4 f = *(const float4*)p;
        r.v0 = (int)(f.x * 255.0f);
        r.v1 = (int)(f.y * 255.0f);
        r.v2 = (int)(f.z * 255.0f);
        r.v3 = (int)(f.w * 255.0f);
    } else {
        r.v0 = r.v1 = r.v2 = r.v3 = 0;
    }
    int ei = (int)(e * 255.0f);
    int up = __shfl_up_sync(0xffffffffu, r.v3, 1);
    int dn = __shfl_down_sync(0xffffffffu, r.v0, 1);
    r.vl = (lane == 0)  ? (valid && lv ? ei : 0) : up;
    r.vr = (lane == 31) ? (valid && rv ? ei : 0) : dn;
    if (!valid) { r.vl = 0; r.vr = 0; }
    return r;
}

template<bool SPEC>
__device__ __forceinline__ void hist_body(const float* __restrict__ p, int ry0,
                                          int* __restrict__ hist,
                                          int lane, bool lv, bool rv) {
    Row6 t = load_row(p, ry0 > 0, lane, lv, rv);         p += WW;
    Row6 m = load_row(p, true, lane, lv, rv);            p += WW;

    int st0 = t.vl + t.v0 + t.v1, st1 = t.v0 + t.v1 + t.v2;
    int st2 = t.v1 + t.v2 + t.v3, st3 = t.v2 + t.v3 + t.vr;
    int sm0 = m.vl + m.v1, sm1 = m.v0 + m.v2;
    int sm2 = m.v1 + m.v3, sm3 = m.v2 + m.vr;
    int c0 = m.v0, c1 = m.v1, c2 = m.v2, c3 = m.v3;

    #pragma unroll 1
    for (int rb = 0; rb < TH; rb += 4) {
        // front-load 4 rows: 4 independent LDG.128 in flight before any use
        Row6 b[4];
        #pragma unroll
        for (int j = 0; j < 4; ++j)
            b[j] = load_row(p + j * WW, ry0 + rb + j + 1 < HH, lane, lv, rv);
        p += 4 * WW;

        #pragma unroll
        for (int j = 0; j < 4; ++j) {
            int sb0 = b[j].vl + b[j].v0 + b[j].v1;
            int sb1 = b[j].v0 + b[j].v1 + b[j].v2;
            int sb2 = b[j].v1 + b[j].v2 + b[j].v3;
            int sb3 = b[j].v2 + b[j].v3 + b[j].vr;

            int n0 = st0 + sm0 + sb0;
            int n1 = st1 + sm1 + sb1;
            int n2 = st2 + sm2 + sb2;
            int n3 = st3 + sm3 + sb3;

            // (nb*13108)>>16 == trunc(nb/5); 21846 -> trunc(nb/3)
            int mul = 13108;
            if (SPEC) {
                int gr = ry0 + rb + j;
                mul = (gr == 0 || gr == HH - 1) ? 21846 : 13108;
            }
            atomicAdd(&hist[(c0 << 9) + ((n0 * mul) >> 16)], 1);
            atomicAdd(&hist[(c1 << 9) + ((n1 * mul) >> 16)], 1);
            atomicAdd(&hist[(c2 << 9) + ((n2 * mul) >> 16)], 1);
            atomicAdd(&hist[(c3 << 9) + ((n3 * mul) >> 16)], 1);

            st0 = sm0 + c0; st1 = sm1 + c1; st2 = sm2 + c2; st3 = sm3 + c3;
            sm0 = sb0 - b[j].v0; sm1 = sb1 - b[j].v1;
            sm2 = sb2 - b[j].v2; sm3 = sb3 - b[j].v3;
            c0 = b[j].v0; c1 = b[j].v1; c2 = b[j].v2; c3 = b[j].v3;
        }
    }
}

__global__ __launch_bounds__(256) void k_hist(const float* __restrict__ x, int B) {
    const int img = blockIdx.z;
    const int ry0 = blockIdx.y * TH;
    const int c    = threadIdx.x * 4;           // 256 threads * 4 = 1024 cols
    const int lane = threadIdx.x & 31;
    const bool lv = (c > 0);
    const bool rv = (c + 4 < WW);

    const float* p = x + (size_t)img * (HH * (size_t)WW) + (size_t)(ry0 - 1) * WW + c;
    int* hist = g_hist + img * NB;

    const bool spec = (img == 0 || img == B - 1) &&
                      (blockIdx.y == 0 || blockIdx.y == NSTRIPE - 1);
    if (spec) hist_body<true >(p, ry0, hist, lane, lv, rv);
    else      hist_body<false>(p, ry0, hist, lane, lv, rv);
}

// ---------------------------------------------------------------- entropy (+ final)
// Read-only over the histogram. Small counts resolve via a 4KB smem LUT of
// c*log2(c) (lut[0]=0 removes the zero-bin branch); c>=LUTN falls back to
// the identical MUFU expression (same bits, deterministic).
__global__ __launch_bounds__(256) void k_entropy(float* __restrict__ out, int B) {
    __shared__ float lut[LUTN];
    for (int i = threadIdx.x; i < LUTN; i += 256)
        lut[i] = i ? (float)i * __log2f((float)i) : 0.0f;
    __syncthreads();

    const int img = blockIdx.y;
    const int4* h = (const int4*)(g_hist + img * NB);
    const int n4 = NB / 4;

    float acc = 0.0f;
    for (int i = blockIdx.x * blockDim.x + threadIdx.x; i < n4;
         i += gridDim.x * blockDim.x) {
        int4 v = h[i];
        #pragma unroll
        for (int k = 0; k < 4; ++k) {
            int c = (&v.x)[k];
            acc += ((unsigned)c < LUTN) ? lut[c]
                                        : (float)c * __log2f((float)c);
        }
    }

    __shared__ float sm[256];
    __shared__ bool last;
    sm[threadIdx.x] = acc;
    __syncthreads();
    for (int s = 128; s > 0; s >>= 1) {
        if (threadIdx.x < s) sm[threadIdx.x] += sm[threadIdx.x + s];
        __syncthreads();
    }
    if (threadIdx.x == 0) {
        g_partial[img * EBLK + blockIdx.x] = sm[0];   // fixed slot: deterministic
        __threadfence();
        unsigned v = atomicAdd(&g_done, 1u);
        last = (v == gridDim.x * gridDim.y - 1);
    }
    __syncthreads();

    if (last) {
        const int t = threadIdx.x;
        float e = 0.0f;
        if (t < B) {
            float s = 0.0f;
            #pragma unroll
            for (int j = 0; j < EBLK; ++j) s += g_partial[t * EBLK + j];
            e = 20.0f - s * (1.0f / 1048576.0f);   // log2(2^20) - sum/2^20
        }
        __syncthreads();
        sm[t] = (t < 64) ? e : 0.0f;
        __syncthreads();
        for (int s = 32; s > 0; s >>= 1) {
            if (t < s) sm[t] += sm[t + s];
            __syncthreads();
        }
        if (t == 0) {
            out[0] = sm[0] / (float)B;
            g_done = 0;                 // reset for next graph replay
        }
    }
}

// ---------------------------------------------------------------- launch
extern "C" void kernel_launch(void* const* d_in, const int* in_sizes, int n_in,
                              void* d_out, int out_size) {
    const float* x = (const float*)d_in[0];
    int B = in_sizes[0] / (HH * WW);
    if (B > NIMG_MAX) B = NIMG_MAX;

    // bulk zero of the used histogram range: captured as a graph memset node
    void* hp = nullptr;
    cudaGetSymbolAddress(&hp, g_hist);
    cudaMemsetAsync(hp, 0, (size_t)B * NB * sizeof(int));

    dim3 gh(1, NSTRIPE, B);          // 1 x 16 x 64 = 1024 blocks
    k_hist<<<gh, 256>>>(x, B);

    k_entropy<<<dim3(EBLK, B), 256>>>((float*)d_out, B);
}

// round 14
// speedup vs baseline: 1.6936x; 1.0561x over previous
#include <cuda_runtime.h>

#define NIMG_MAX 64
#define HH 1024
#define WW 1024
#define NB 131072         // 256 * 512 bins per image
#define EBLK 16           // entropy partial blocks per image
#define TH 32             // rows per stripe (2048 blocks: better SM balance)
#define NSTRIPE (HH / TH)

// 32 MB histogram scratch (zeroed by a graph memset node each invocation).
// Phase discipline (hard-won): memset writes it, k_hist REDs it, k_entropy
// reads it — never concurrently (concurrent read poisons the LTS atomic pipe).
__device__ __align__(16) int   g_hist[NIMG_MAX * NB];
__device__ __align__(16) float g_partial[NIMG_MAX * EBLK];
__device__ unsigned int g_done;   // zero-init; reset by last entropy block

// ---------------------------------------------------------------- histogram
// Register-resident sliding window, 4-row software pipeline.
// Halo columns via warp SHFL; lanes 0/31 use a 1-sector predicated LDG.

struct Row6 { int v0, v1, v2, v3, vl, vr; };

__device__ __forceinline__ Row6 load_row(const float* __restrict__ p, bool valid,
                                         int lane, bool lv, bool rv) {
    Row6 r;
    float e = 0.0f;
    if (valid) {
        if (lane == 0  && lv) e = __ldg(p - 1);
        if (lane == 31 && rv) e = __ldg(p + 4);
        float4 f = *(const float4*)p;
        r.v0 = (int)(f.x * 255.0f);
        r.v1 = (int)(f.y * 255.0f);
        r.v2 = (int)(f.z * 255.0f);
        r.v3 = (int)(f.w * 255.0f);
    } else {
        r.v0 = r.v1 = r.v2 = r.v3 = 0;
    }
    int ei = (int)(e * 255.0f);
    int up = __shfl_up_sync(0xffffffffu, r.v3, 1);
    int dn = __shfl_down_sync(0xffffffffu, r.v0, 1);
    r.vl = (lane == 0)  ? (valid && lv ? ei : 0) : up;
    r.vr = (lane == 31) ? (valid && rv ? ei : 0) : dn;
    if (!valid) { r.vl = 0; r.vr = 0; }
    return r;
}

template<bool SPEC>
__device__ __forceinline__ void hist_body(const float* __restrict__ p, int ry0,
                                          int* __restrict__ hist,
                                          int lane, bool lv, bool rv) {
    Row6 t = load_row(p, ry0 > 0, lane, lv, rv);         p += WW;
    Row6 m = load_row(p, true, lane, lv, rv);            p += WW;

    int st0 = t.vl + t.v0 + t.v1, st1 = t.v0 + t.v1 + t.v2;
    int st2 = t.v1 + t.v2 + t.v3, st3 = t.v2 + t.v3 + t.vr;
    int sm0 = m.vl + m.v1, sm1 = m.v0 + m.v2;
    int sm2 = m.v1 + m.v3, sm3 = m.v2 + m.vr;
    int c0 = m.v0, c1 = m.v1, c2 = m.v2, c3 = m.v3;

    #pragma unroll 1
    for (int rb = 0; rb < TH; rb += 4) {
        // front-load 4 rows: 4 independent LDG.128 in flight before any use
        Row6 b[4];
        #pragma unroll
        for (int j = 0; j < 4; ++j)
            b[j] = load_row(p + j * WW, ry0 + rb + j + 1 < HH, lane, lv, rv);
        p += 4 * WW;

        #pragma unroll
        for (int j = 0; j < 4; ++j) {
            int sb0 = b[j].vl + b[j].v0 + b[j].v1;
            int sb1 = b[j].v0 + b[j].v1 + b[j].v2;
            int sb2 = b[j].v1 + b[j].v2 + b[j].v3;
            int sb3 = b[j].v2 + b[j].v3 + b[j].vr;

            int n0 = st0 + sm0 + sb0;
            int n1 = st1 + sm1 + sb1;
            int n2 = st2 + sm2 + sb2;
            int n3 = st3 + sm3 + sb3;

            // (nb*13108)>>16 == trunc(nb/5); 21846 -> trunc(nb/3)
            int mul = 13108;
            if (SPEC) {
                int gr = ry0 + rb + j;
                mul = (gr == 0 || gr == HH - 1) ? 21846 : 13108;
            }
            atomicAdd(&hist[(c0 << 9) + ((n0 * mul) >> 16)], 1);
            atomicAdd(&hist[(c1 << 9) + ((n1 * mul) >> 16)], 1);
            atomicAdd(&hist[(c2 << 9) + ((n2 * mul) >> 16)], 1);
            atomicAdd(&hist[(c3 << 9) + ((n3 * mul) >> 16)], 1);

            st0 = sm0 + c0; st1 = sm1 + c1; st2 = sm2 + c2; st3 = sm3 + c3;
            sm0 = sb0 - b[j].v0; sm1 = sb1 - b[j].v1;
            sm2 = sb2 - b[j].v2; sm3 = sb3 - b[j].v3;
            c0 = b[j].v0; c1 = b[j].v1; c2 = b[j].v2; c3 = b[j].v3;
        }
    }
}

__global__ __launch_bounds__(256) void k_hist(const float* __restrict__ x, int B) {
    const int img = blockIdx.z;
    const int ry0 = blockIdx.y * TH;
    const int c    = threadIdx.x * 4;           // 256 threads * 4 = 1024 cols
    const int lane = threadIdx.x & 31;
    const bool lv = (c > 0);
    const bool rv = (c + 4 < WW);

    const float* p = x + (size_t)img * (HH * (size_t)WW) + (size_t)(ry0 - 1) * WW + c;
    int* hist = g_hist + img * NB;

    const bool spec = (img == 0 || img == B - 1) &&
                      (blockIdx.y == 0 || blockIdx.y == NSTRIPE - 1);
    if (spec) hist_body<true >(p, ry0, hist, lane, lv, rv);
    else      hist_body<false>(p, ry0, hist, lane, lv, rv);
}

// ---------------------------------------------------------------- entropy (+ final)
// Read-only over the histogram (measured-best form: branch + MUFU).
__global__ __launch_bounds__(256) void k_entropy(float* __restrict__ out, int B) {
    const int img = blockIdx.y;
    const int4* h = (const int4*)(g_hist + img * NB);
    const int n4 = NB / 4;

    float acc = 0.0f;
    for (int i = blockIdx.x * blockDim.x + threadIdx.x; i < n4;
         i += gridDim.x * blockDim.x) {
        int4 v = h[i];
        if (v.x) acc += (float)v.x * __log2f((float)v.x);
        if (v.y) acc += (float)v.y * __log2f((float)v.y);
        if (v.z) acc += (float)v.z * __log2f((float)v.z);
        if (v.w) acc += (float)v.w * __log2f((float)v.w);
    }

    __shared__ float sm[256];
    __shared__ bool last;
    sm[threadIdx.x] = acc;
    __syncthreads();
    for (int s = 128; s > 0; s >>= 1) {
        if (threadIdx.x < s) sm[threadIdx.x] += sm[threadIdx.x + s];
        __syncthreads();
    }
    if (threadIdx.x == 0) {
        g_partial[img * EBLK + blockIdx.x] = sm[0];   // fixed slot: deterministic
        __threadfence();
        unsigned v = atomicAdd(&g_done, 1u);
        last = (v == gridDim.x * gridDim.y - 1);
    }
    __syncthreads();

    if (last) {
        const int t = threadIdx.x;
        float e = 0.0f;
        if (t < B) {
            float s = 0.0f;
            #pragma unroll
            for (int j = 0; j < EBLK; ++j) s += g_partial[t * EBLK + j];
            e = 20.0f - s * (1.0f / 1048576.0f);   // log2(2^20) - sum/2^20
        }
        __syncthreads();
        sm[t] = (t < 64) ? e : 0.0f;
        __syncthreads();
        for (int s = 32; s > 0; s >>= 1) {
            if (t < s) sm[t] += sm[t + s];
            __syncthreads();
        }
        if (t == 0) {
            out[0] = sm[0] / (float)B;
            g_done = 0;                 // reset for next graph replay
        }
    }
}

// ---------------------------------------------------------------- launch
extern "C" void kernel_launch(void* const* d_in, const int* in_sizes, int n_in,
                              void* d_out, int out_size) {
    const float* x = (const float*)d_in[0];
    int B = in_sizes[0] / (HH * WW);
    if (B > NIMG_MAX) B = NIMG_MAX;

    // bulk zero of the used histogram range: captured as a graph memset node
    void* hp = nullptr;
    cudaGetSymbolAddress(&hp, g_hist);
    cudaMemsetAsync(hp, 0, (size_t)B * NB * sizeof(int));

    dim3 gh(1, NSTRIPE, B);          // 1 x 32 x 64 = 2048 blocks
    k_hist<<<gh, 256>>>(x, B);

    k_entropy<<<dim3(EBLK, B), 256>>>((float*)d_out, B);
}